// round 11
// baseline (speedup 1.0000x reference)
#include <cuda_runtime.h>

#define Bn   16
#define Cn   256
#define Hn   64
#define Wn   64
#define Kn   4
#define On   256
#define HIDn 65
#define TEMP 34.0f

// ---------------- scratch (no allocations allowed) ----------------
__device__ float g_pooled[Bn * Cn];
__device__ float g_att[Bn * Kn];

// ---------------- packed f32x2 helpers (sm_103a) ----------------
__device__ __forceinline__ unsigned long long pk2(float lo, float hi) {
    unsigned long long r;
    asm("mov.b64 %0, {%1, %2};" : "=l"(r) : "f"(lo), "f"(hi));
    return r;
}
__device__ __forceinline__ void fma2(unsigned long long& d,
                                     unsigned long long a,
                                     unsigned long long b) {
    asm("fma.rn.f32x2 %0, %1, %2, %0;" : "+l"(d) : "l"(a), "l"(b));
}
__device__ __forceinline__ float2 unpk2(unsigned long long v) {
    float2 r;
    asm("mov.b64 {%0, %1}, %2;" : "=f"(r.x), "=f"(r.y) : "l"(v));
    return r;
}

// ---------------- stage 1: global average pool ----------------
// one block per (b, c): reduce 64*64 = 4096 floats
__global__ void pool_kernel(const float* __restrict__ x) {
    const int bc = blockIdx.x;                       // 0 .. B*C-1
    const float* p = x + (size_t)bc * (Hn * Wn);
    float s = 0.f;
    for (int i = threadIdx.x; i < Hn * Wn; i += 256) s += p[i];
    // warp reduce
    #pragma unroll
    for (int off = 16; off; off >>= 1) s += __shfl_down_sync(0xffffffffu, s, off);
    __shared__ float red[8];
    if ((threadIdx.x & 31) == 0) red[threadIdx.x >> 5] = s;
    __syncthreads();
    if (threadIdx.x < 8) {
        s = red[threadIdx.x];
        #pragma unroll
        for (int off = 4; off; off >>= 1) s += __shfl_down_sync(0xffu, s, off);
        if (threadIdx.x == 0) g_pooled[bc] = s * (1.0f / (Hn * Wn));
    }
}

// ---------------- stage 2: attention MLP + softmax ----------------
// one block per batch sample
__global__ void att_kernel(const float* __restrict__ w_fc1,
                           const float* __restrict__ w_fc2,
                           const float* __restrict__ b_fc2) {
    const int b = blockIdx.x;
    __shared__ float ps[Cn];
    __shared__ float hs[HIDn];
    __shared__ float lg[Kn];
    for (int i = threadIdx.x; i < Cn; i += 128) ps[i] = g_pooled[b * Cn + i];
    __syncthreads();
    if (threadIdx.x < HIDn) {
        float s = 0.f;
        const float* wr = w_fc1 + threadIdx.x * Cn;
        for (int c = 0; c < Cn; c++) s = fmaf(ps[c], wr[c], s);
        hs[threadIdx.x] = fmaxf(s, 0.f);
    }
    __syncthreads();
    if (threadIdx.x < Kn) {
        float s = b_fc2[threadIdx.x];
        const float* wr = w_fc2 + threadIdx.x * HIDn;
        for (int j = 0; j < HIDn; j++) s = fmaf(hs[j], wr[j], s);
        lg[threadIdx.x] = s * (1.0f / TEMP);
    }
    __syncthreads();
    if (threadIdx.x == 0) {
        float m = fmaxf(fmaxf(lg[0], lg[1]), fmaxf(lg[2], lg[3]));
        float e0 = expf(lg[0] - m), e1 = expf(lg[1] - m);
        float e2 = expf(lg[2] - m), e3 = expf(lg[3] - m);
        float inv = 1.0f / (e0 + e1 + e2 + e3);
        g_att[b * 4 + 0] = e0 * inv;
        g_att[b * 4 + 1] = e1 * inv;
        g_att[b * 4 + 2] = e2 * inv;
        g_att[b * 4 + 3] = e3 * inv;
    }
}

// ---------------- stage 3: dynamic conv (implicit GEMM) ----------------
// block: (spatial tile 16x16, O tile 64, batch). 256 threads.
// warp = one group of 8 output channels; lane = one 8-pixel row segment.
// weights aggregated on the fly from the 4 base kernels (L2-resident).
__global__ __launch_bounds__(256, 2)
void conv_kernel(const float* __restrict__ x,
                 const float* __restrict__ weight,
                 const float* __restrict__ bias,
                 float* __restrict__ out) {
    const int st = blockIdx.x;           // 0..15 spatial tile
    const int ot = blockIdx.y;           // 0..3  output-channel tile
    const int b  = blockIdx.z;           // 0..15 batch
    const int th0 = (st >> 2) << 4;
    const int tw0 = (st & 3) << 4;
    const int obase = ot << 6;

    __shared__ float xs[8][18][19];      // 8 channels, 18x18 halo, stride 19 (conflict-free)
    __shared__ float ws[64][72];         // [o][c*9+tap]; store addr == idx (conflict-free), load = broadcast

    const int tid  = threadIdx.x;
    const int og   = tid >> 5;           // warp id = o-group (8 o's)
    const int pg   = tid & 31;           // pixel group
    const int rl   = pg >> 1;            // row within tile 0..15
    const int colb = (pg & 1) << 3;      // 0 or 8

    const float a0 = g_att[b * 4 + 0], a1 = g_att[b * 4 + 1];
    const float a2 = g_att[b * 4 + 2], a3 = g_att[b * 4 + 3];

    // accumulators: 8 o x 4 pixel-pairs, init with aggregated bias
    unsigned long long acc[8][4];
    #pragma unroll
    for (int oi = 0; oi < 8; oi++) {
        int o = obase + (og << 3) + oi;
        float bb = a0 * bias[o] + a1 * bias[On + o] + a2 * bias[2 * On + o] + a3 * bias[3 * On + o];
        unsigned long long bp = pk2(bb, bb);
        #pragma unroll
        for (int p = 0; p < 4; p++) acc[oi][p] = bp;
    }

    const size_t ksz = (size_t)On * Cn * 9;

    for (int cb = 0; cb < Cn; cb += 8) {
        // ---- load x halo tile (8 x 18 x 18) ----
        for (int idx = tid; idx < 8 * 18 * 18; idx += 256) {
            int cc  = idx / 324;
            int rem = idx - cc * 324;
            int r   = rem / 18;
            int col = rem - r * 18;
            int gh = th0 - 1 + r, gw = tw0 - 1 + col;
            float v = 0.f;
            if ((unsigned)gh < (unsigned)Hn && (unsigned)gw < (unsigned)Wn)
                v = x[(((size_t)b * Cn + cb + cc) * Hn + gh) * Wn + gw];
            xs[cc][r][col] = v;
        }
        // ---- load + aggregate weights: ws[o][cc*9+tap] = sum_k att_k * W_k ----
        for (int idx = tid; idx < 64 * 72; idx += 256) {
            int o  = idx / 72;
            int ct = idx - o * 72;       // contiguous (c,tap) run of 72 per o
            size_t base = ((size_t)(obase + o) * Cn + cb) * 9 + ct;
            float v = a0 * weight[base]
                    + a1 * weight[base + ksz]
                    + a2 * weight[base + 2 * ksz]
                    + a3 * weight[base + 3 * ksz];
            ws[o][ct] = v;
        }
        __syncthreads();

        // ---- compute: 8 channels x 3x3 taps, packed f32x2 FMA ----
        #pragma unroll 1
        for (int cc = 0; cc < 8; cc++) {
            #pragma unroll
            for (int i = 0; i < 3; i++) {
                float xr[10];
                #pragma unroll
                for (int t = 0; t < 10; t++) xr[t] = xs[cc][rl + i][colb + t];
                #pragma unroll
                for (int j = 0; j < 3; j++) {
                    unsigned long long xp0 = pk2(xr[j + 0], xr[j + 1]);
                    unsigned long long xp1 = pk2(xr[j + 2], xr[j + 3]);
                    unsigned long long xp2 = pk2(xr[j + 4], xr[j + 5]);
                    unsigned long long xp3 = pk2(xr[j + 6], xr[j + 7]);
                    int ct = cc * 9 + i * 3 + j;
                    #pragma unroll
                    for (int oi = 0; oi < 8; oi++) {
                        float w = ws[(og << 3) + oi][ct];   // broadcast within warp
                        unsigned long long wp = pk2(w, w);
                        fma2(acc[oi][0], xp0, wp);
                        fma2(acc[oi][1], xp1, wp);
                        fma2(acc[oi][2], xp2, wp);
                        fma2(acc[oi][3], xp3, wp);
                    }
                }
            }
        }
        __syncthreads();
    }

    // ---- store: 8 o x 8 contiguous pixels (8-aligned -> STG.64) ----
    #pragma unroll
    for (int oi = 0; oi < 8; oi++) {
        int o = obase + (og << 3) + oi;
        float2* op = (float2*)(out + (((size_t)b * On + o) * Hn + th0 + rl) * Wn + tw0 + colb);
        #pragma unroll
        for (int p = 0; p < 4; p++) op[p] = unpk2(acc[oi][p]);
    }
}

// ---------------- launch ----------------
extern "C" void kernel_launch(void* const* d_in, const int* in_sizes, int n_in,
                              void* d_out, int out_size) {
    const float* x      = (const float*)d_in[0];
    const float* w_fc1  = (const float*)d_in[1];
    const float* w_fc2  = (const float*)d_in[2];
    const float* b_fc2  = (const float*)d_in[3];
    const float* weight = (const float*)d_in[4];
    const float* bias   = (const float*)d_in[5];
    float* out = (float*)d_out;

    pool_kernel<<<Bn * Cn, 256>>>(x);
    att_kernel<<<Bn, 128>>>(w_fc1, w_fc2, b_fc2);
    dim3 grid(16, 4, Bn);
    conv_kernel<<<grid, 256>>>(x, weight, bias, out);
}

// round 12
// speedup vs baseline: 1.0002x; 1.0002x over previous
#include <cuda_runtime.h>

#define Bn   16
#define Cn   256
#define Hn   64
#define Wn   64
#define Kn   4
#define On   256
#define HIDn 65
#define TEMP 34.0f

// ---------------- scratch (no allocations allowed) ----------------
__device__ float g_pooled[Bn * Cn];
__device__ float g_att[Bn * Kn];

// ---------------- packed f32x2 helpers (sm_103a) ----------------
__device__ __forceinline__ unsigned long long pk2(float lo, float hi) {
    unsigned long long r;
    asm("mov.b64 %0, {%1, %2};" : "=l"(r) : "f"(lo), "f"(hi));
    return r;
}
__device__ __forceinline__ void fma2(unsigned long long& d,
                                     unsigned long long a,
                                     unsigned long long b) {
    asm("fma.rn.f32x2 %0, %1, %2, %0;" : "+l"(d) : "l"(a), "l"(b));
}
__device__ __forceinline__ float2 unpk2(unsigned long long v) {
    float2 r;
    asm("mov.b64 {%0, %1}, %2;" : "=f"(r.x), "=f"(r.y) : "l"(v));
    return r;
}

// ---------------- stage 1: global average pool ----------------
// one block per (b, c): reduce 64*64 = 4096 floats
__global__ void pool_kernel(const float* __restrict__ x) {
    const int bc = blockIdx.x;                       // 0 .. B*C-1
    const float* p = x + (size_t)bc * (Hn * Wn);
    float s = 0.f;
    for (int i = threadIdx.x; i < Hn * Wn; i += 256) s += p[i];
    // warp reduce
    #pragma unroll
    for (int off = 16; off; off >>= 1) s += __shfl_down_sync(0xffffffffu, s, off);
    __shared__ float red[8];
    if ((threadIdx.x & 31) == 0) red[threadIdx.x >> 5] = s;
    __syncthreads();
    if (threadIdx.x < 8) {
        s = red[threadIdx.x];
        #pragma unroll
        for (int off = 4; off; off >>= 1) s += __shfl_down_sync(0xffu, s, off);
        if (threadIdx.x == 0) g_pooled[bc] = s * (1.0f / (Hn * Wn));
    }
}

// ---------------- stage 2: attention MLP + softmax ----------------
// one block per batch sample
__global__ void att_kernel(const float* __restrict__ w_fc1,
                           const float* __restrict__ w_fc2,
                           const float* __restrict__ b_fc2) {
    const int b = blockIdx.x;
    __shared__ float ps[Cn];
    __shared__ float hs[HIDn];
    __shared__ float lg[Kn];
    for (int i = threadIdx.x; i < Cn; i += 128) ps[i] = g_pooled[b * Cn + i];
    __syncthreads();
    if (threadIdx.x < HIDn) {
        float s = 0.f;
        const float* wr = w_fc1 + threadIdx.x * Cn;
        for (int c = 0; c < Cn; c++) s = fmaf(ps[c], wr[c], s);
        hs[threadIdx.x] = fmaxf(s, 0.f);
    }
    __syncthreads();
    if (threadIdx.x < Kn) {
        float s = b_fc2[threadIdx.x];
        const float* wr = w_fc2 + threadIdx.x * HIDn;
        for (int j = 0; j < HIDn; j++) s = fmaf(hs[j], wr[j], s);
        lg[threadIdx.x] = s * (1.0f / TEMP);
    }
    __syncthreads();
    if (threadIdx.x == 0) {
        float m = fmaxf(fmaxf(lg[0], lg[1]), fmaxf(lg[2], lg[3]));
        float e0 = expf(lg[0] - m), e1 = expf(lg[1] - m);
        float e2 = expf(lg[2] - m), e3 = expf(lg[3] - m);
        float inv = 1.0f / (e0 + e1 + e2 + e3);
        g_att[b * 4 + 0] = e0 * inv;
        g_att[b * 4 + 1] = e1 * inv;
        g_att[b * 4 + 2] = e2 * inv;
        g_att[b * 4 + 3] = e3 * inv;
    }
}

// ---------------- stage 3: dynamic conv (implicit GEMM) ----------------
// block: (spatial tile 16x16, O tile 64, batch). 256 threads.
// warp = one group of 8 output channels; lane = one 8-pixel row segment.
// weights aggregated on the fly from the 4 base kernels (L2-resident).
__global__ __launch_bounds__(256, 2)
void conv_kernel(const float* __restrict__ x,
                 const float* __restrict__ weight,
                 const float* __restrict__ bias,
                 float* __restrict__ out) {
    const int st = blockIdx.x;           // 0..15 spatial tile
    const int ot = blockIdx.y;           // 0..3  output-channel tile
    const int b  = blockIdx.z;           // 0..15 batch
    const int th0 = (st >> 2) << 4;
    const int tw0 = (st & 3) << 4;
    const int obase = ot << 6;

    __shared__ float xs[8][18][19];      // 8 channels, 18x18 halo, stride 19 (conflict-free)
    __shared__ float ws[64][72];         // [o][c*9+tap]; store addr == idx (conflict-free), load = broadcast

    const int tid  = threadIdx.x;
    const int og   = tid >> 5;           // warp id = o-group (8 o's)
    const int pg   = tid & 31;           // pixel group
    const int rl   = pg >> 1;            // row within tile 0..15
    const int colb = (pg & 1) << 3;      // 0 or 8

    const float a0 = g_att[b * 4 + 0], a1 = g_att[b * 4 + 1];
    const float a2 = g_att[b * 4 + 2], a3 = g_att[b * 4 + 3];

    // accumulators: 8 o x 4 pixel-pairs, init with aggregated bias
    unsigned long long acc[8][4];
    #pragma unroll
    for (int oi = 0; oi < 8; oi++) {
        int o = obase + (og << 3) + oi;
        float bb = a0 * bias[o] + a1 * bias[On + o] + a2 * bias[2 * On + o] + a3 * bias[3 * On + o];
        unsigned long long bp = pk2(bb, bb);
        #pragma unroll
        for (int p = 0; p < 4; p++) acc[oi][p] = bp;
    }

    const size_t ksz = (size_t)On * Cn * 9;

    for (int cb = 0; cb < Cn; cb += 8) {
        // ---- load x halo tile (8 x 18 x 18) ----
        for (int idx = tid; idx < 8 * 18 * 18; idx += 256) {
            int cc  = idx / 324;
            int rem = idx - cc * 324;
            int r   = rem / 18;
            int col = rem - r * 18;
            int gh = th0 - 1 + r, gw = tw0 - 1 + col;
            float v = 0.f;
            if ((unsigned)gh < (unsigned)Hn && (unsigned)gw < (unsigned)Wn)
                v = x[(((size_t)b * Cn + cb + cc) * Hn + gh) * Wn + gw];
            xs[cc][r][col] = v;
        }
        // ---- load + aggregate weights: ws[o][cc*9+tap] = sum_k att_k * W_k ----
        for (int idx = tid; idx < 64 * 72; idx += 256) {
            int o  = idx / 72;
            int ct = idx - o * 72;       // contiguous (c,tap) run of 72 per o
            size_t base = ((size_t)(obase + o) * Cn + cb) * 9 + ct;
            float v = a0 * weight[base]
                    + a1 * weight[base + ksz]
                    + a2 * weight[base + 2 * ksz]
                    + a3 * weight[base + 3 * ksz];
            ws[o][ct] = v;
        }
        __syncthreads();

        // ---- compute: 8 channels x 3x3 taps, packed f32x2 FMA ----
        #pragma unroll 1
        for (int cc = 0; cc < 8; cc++) {
            #pragma unroll
            for (int i = 0; i < 3; i++) {
                float xr[10];
                #pragma unroll
                for (int t = 0; t < 10; t++) xr[t] = xs[cc][rl + i][colb + t];
                #pragma unroll
                for (int j = 0; j < 3; j++) {
                    unsigned long long xp0 = pk2(xr[j + 0], xr[j + 1]);
                    unsigned long long xp1 = pk2(xr[j + 2], xr[j + 3]);
                    unsigned long long xp2 = pk2(xr[j + 4], xr[j + 5]);
                    unsigned long long xp3 = pk2(xr[j + 6], xr[j + 7]);
                    int ct = cc * 9 + i * 3 + j;
                    #pragma unroll
                    for (int oi = 0; oi < 8; oi++) {
                        float w = ws[(og << 3) + oi][ct];   // broadcast within warp
                        unsigned long long wp = pk2(w, w);
                        fma2(acc[oi][0], xp0, wp);
                        fma2(acc[oi][1], xp1, wp);
                        fma2(acc[oi][2], xp2, wp);
                        fma2(acc[oi][3], xp3, wp);
                    }
                }
            }
        }
        __syncthreads();
    }

    // ---- store: 8 o x 8 contiguous pixels (8-aligned -> STG.64) ----
    #pragma unroll
    for (int oi = 0; oi < 8; oi++) {
        int o = obase + (og << 3) + oi;
        float2* op = (float2*)(out + (((size_t)b * On + o) * Hn + th0 + rl) * Wn + tw0 + colb);
        #pragma unroll
        for (int p = 0; p < 4; p++) op[p] = unpk2(acc[oi][p]);
    }
}

// ---------------- launch ----------------
extern "C" void kernel_launch(void* const* d_in, const int* in_sizes, int n_in,
                              void* d_out, int out_size) {
    const float* x      = (const float*)d_in[0];
    const float* w_fc1  = (const float*)d_in[1];
    const float* w_fc2  = (const float*)d_in[2];
    const float* b_fc2  = (const float*)d_in[3];
    const float* weight = (const float*)d_in[4];
    const float* bias   = (const float*)d_in[5];
    float* out = (float*)d_out;

    pool_kernel<<<Bn * Cn, 256>>>(x);
    att_kernel<<<Bn, 128>>>(w_fc1, w_fc2, b_fc2);
    dim3 grid(16, 4, Bn);
    conv_kernel<<<grid, 256>>>(x, weight, bias, out);
}

// round 13
// speedup vs baseline: 1.0012x; 1.0010x over previous
#include <cuda_runtime.h>

#define Bn   16
#define Cn   256
#define Hn   64
#define Wn   64
#define Kn   4
#define On   256
#define HIDn 65
#define TEMP 34.0f

// ---------------- scratch (no allocations allowed) ----------------
__device__ float g_pooled[Bn * Cn];
__device__ float g_att[Bn * Kn];

// ---------------- packed f32x2 helpers (sm_103a) ----------------
__device__ __forceinline__ unsigned long long pk2(float lo, float hi) {
    unsigned long long r;
    asm("mov.b64 %0, {%1, %2};" : "=l"(r) : "f"(lo), "f"(hi));
    return r;
}
__device__ __forceinline__ void fma2(unsigned long long& d,
                                     unsigned long long a,
                                     unsigned long long b) {
    asm("fma.rn.f32x2 %0, %1, %2, %0;" : "+l"(d) : "l"(a), "l"(b));
}
__device__ __forceinline__ float2 unpk2(unsigned long long v) {
    float2 r;
    asm("mov.b64 {%0, %1}, %2;" : "=f"(r.x), "=f"(r.y) : "l"(v));
    return r;
}

// ---------------- stage 1: global average pool ----------------
// one block per (b, c): reduce 64*64 = 4096 floats
__global__ void pool_kernel(const float* __restrict__ x) {
    const int bc = blockIdx.x;                       // 0 .. B*C-1
    const float* p = x + (size_t)bc * (Hn * Wn);
    float s = 0.f;
    for (int i = threadIdx.x; i < Hn * Wn; i += 256) s += p[i];
    // warp reduce
    #pragma unroll
    for (int off = 16; off; off >>= 1) s += __shfl_down_sync(0xffffffffu, s, off);
    __shared__ float red[8];
    if ((threadIdx.x & 31) == 0) red[threadIdx.x >> 5] = s;
    __syncthreads();
    if (threadIdx.x < 8) {
        s = red[threadIdx.x];
        #pragma unroll
        for (int off = 4; off; off >>= 1) s += __shfl_down_sync(0xffu, s, off);
        if (threadIdx.x == 0) g_pooled[bc] = s * (1.0f / (Hn * Wn));
    }
}

// ---------------- stage 2: attention MLP + softmax ----------------
// one block per batch sample
__global__ void att_kernel(const float* __restrict__ w_fc1,
                           const float* __restrict__ w_fc2,
                           const float* __restrict__ b_fc2) {
    const int b = blockIdx.x;
    __shared__ float ps[Cn];
    __shared__ float hs[HIDn];
    __shared__ float lg[Kn];
    for (int i = threadIdx.x; i < Cn; i += 128) ps[i] = g_pooled[b * Cn + i];
    __syncthreads();
    if (threadIdx.x < HIDn) {
        float s = 0.f;
        const float* wr = w_fc1 + threadIdx.x * Cn;
        for (int c = 0; c < Cn; c++) s = fmaf(ps[c], wr[c], s);
        hs[threadIdx.x] = fmaxf(s, 0.f);
    }
    __syncthreads();
    if (threadIdx.x < Kn) {
        float s = b_fc2[threadIdx.x];
        const float* wr = w_fc2 + threadIdx.x * HIDn;
        for (int j = 0; j < HIDn; j++) s = fmaf(hs[j], wr[j], s);
        lg[threadIdx.x] = s * (1.0f / TEMP);
    }
    __syncthreads();
    if (threadIdx.x == 0) {
        float m = fmaxf(fmaxf(lg[0], lg[1]), fmaxf(lg[2], lg[3]));
        float e0 = expf(lg[0] - m), e1 = expf(lg[1] - m);
        float e2 = expf(lg[2] - m), e3 = expf(lg[3] - m);
        float inv = 1.0f / (e0 + e1 + e2 + e3);
        g_att[b * 4 + 0] = e0 * inv;
        g_att[b * 4 + 1] = e1 * inv;
        g_att[b * 4 + 2] = e2 * inv;
        g_att[b * 4 + 3] = e3 * inv;
    }
}

// ---------------- stage 3: dynamic conv (implicit GEMM) ----------------
// block: (spatial tile 16x16, O tile 64, batch). 256 threads.
// warp = one group of 8 output channels; lane = one 8-pixel row segment.
// weights aggregated on the fly from the 4 base kernels (L2-resident).
__global__ __launch_bounds__(256, 2)
void conv_kernel(const float* __restrict__ x,
                 const float* __restrict__ weight,
                 const float* __restrict__ bias,
                 float* __restrict__ out) {
    const int st = blockIdx.x;           // 0..15 spatial tile
    const int ot = blockIdx.y;           // 0..3  output-channel tile
    const int b  = blockIdx.z;           // 0..15 batch
    const int th0 = (st >> 2) << 4;
    const int tw0 = (st & 3) << 4;
    const int obase = ot << 6;

    __shared__ float xs[8][18][19];      // 8 channels, 18x18 halo, stride 19 (conflict-free)
    __shared__ float ws[64][72];         // [o][c*9+tap]; store addr == idx (conflict-free), load = broadcast

    const int tid  = threadIdx.x;
    const int og   = tid >> 5;           // warp id = o-group (8 o's)
    const int pg   = tid & 31;           // pixel group
    const int rl   = pg >> 1;            // row within tile 0..15
    const int colb = (pg & 1) << 3;      // 0 or 8

    const float a0 = g_att[b * 4 + 0], a1 = g_att[b * 4 + 1];
    const float a2 = g_att[b * 4 + 2], a3 = g_att[b * 4 + 3];

    // accumulators: 8 o x 4 pixel-pairs, init with aggregated bias
    unsigned long long acc[8][4];
    #pragma unroll
    for (int oi = 0; oi < 8; oi++) {
        int o = obase + (og << 3) + oi;
        float bb = a0 * bias[o] + a1 * bias[On + o] + a2 * bias[2 * On + o] + a3 * bias[3 * On + o];
        unsigned long long bp = pk2(bb, bb);
        #pragma unroll
        for (int p = 0; p < 4; p++) acc[oi][p] = bp;
    }

    const size_t ksz = (size_t)On * Cn * 9;

    for (int cb = 0; cb < Cn; cb += 8) {
        // ---- load x halo tile (8 x 18 x 18) ----
        for (int idx = tid; idx < 8 * 18 * 18; idx += 256) {
            int cc  = idx / 324;
            int rem = idx - cc * 324;
            int r   = rem / 18;
            int col = rem - r * 18;
            int gh = th0 - 1 + r, gw = tw0 - 1 + col;
            float v = 0.f;
            if ((unsigned)gh < (unsigned)Hn && (unsigned)gw < (unsigned)Wn)
                v = x[(((size_t)b * Cn + cb + cc) * Hn + gh) * Wn + gw];
            xs[cc][r][col] = v;
        }
        // ---- load + aggregate weights: ws[o][cc*9+tap] = sum_k att_k * W_k ----
        for (int idx = tid; idx < 64 * 72; idx += 256) {
            int o  = idx / 72;
            int ct = idx - o * 72;       // contiguous (c,tap) run of 72 per o
            size_t base = ((size_t)(obase + o) * Cn + cb) * 9 + ct;
            float v = a0 * weight[base]
                    + a1 * weight[base + ksz]
                    + a2 * weight[base + 2 * ksz]
                    + a3 * weight[base + 3 * ksz];
            ws[o][ct] = v;
        }
        __syncthreads();

        // ---- compute: 8 channels x 3x3 taps, packed f32x2 FMA ----
        #pragma unroll 1
        for (int cc = 0; cc < 8; cc++) {
            #pragma unroll
            for (int i = 0; i < 3; i++) {
                float xr[10];
                #pragma unroll
                for (int t = 0; t < 10; t++) xr[t] = xs[cc][rl + i][colb + t];
                #pragma unroll
                for (int j = 0; j < 3; j++) {
                    unsigned long long xp0 = pk2(xr[j + 0], xr[j + 1]);
                    unsigned long long xp1 = pk2(xr[j + 2], xr[j + 3]);
                    unsigned long long xp2 = pk2(xr[j + 4], xr[j + 5]);
                    unsigned long long xp3 = pk2(xr[j + 6], xr[j + 7]);
                    int ct = cc * 9 + i * 3 + j;
                    #pragma unroll
                    for (int oi = 0; oi < 8; oi++) {
                        float w = ws[(og << 3) + oi][ct];   // broadcast within warp
                        unsigned long long wp = pk2(w, w);
                        fma2(acc[oi][0], xp0, wp);
                        fma2(acc[oi][1], xp1, wp);
                        fma2(acc[oi][2], xp2, wp);
                        fma2(acc[oi][3], xp3, wp);
                    }
                }
            }
        }
        __syncthreads();
    }

    // ---- store: 8 o x 8 contiguous pixels (8-aligned -> STG.64) ----
    #pragma unroll
    for (int oi = 0; oi < 8; oi++) {
        int o = obase + (og << 3) + oi;
        float2* op = (float2*)(out + (((size_t)b * On + o) * Hn + th0 + rl) * Wn + tw0 + colb);
        #pragma unroll
        for (int p = 0; p < 4; p++) op[p] = unpk2(acc[oi][p]);
    }
}

// ---------------- launch ----------------
extern "C" void kernel_launch(void* const* d_in, const int* in_sizes, int n_in,
                              void* d_out, int out_size) {
    const float* x      = (const float*)d_in[0];
    const float* w_fc1  = (const float*)d_in[1];
    const float* w_fc2  = (const float*)d_in[2];
    const float* b_fc2  = (const float*)d_in[3];
    const float* weight = (const float*)d_in[4];
    const float* bias   = (const float*)d_in[5];
    float* out = (float*)d_out;

    pool_kernel<<<Bn * Cn, 256>>>(x);
    att_kernel<<<Bn, 128>>>(w_fc1, w_fc2, b_fc2);
    dim3 grid(16, 4, Bn);
    conv_kernel<<<grid, 256>>>(x, weight, bias, out);
}